// round 6
// baseline (speedup 1.0000x reference)
#include <cuda_runtime.h>
#include <cuda_fp16.h>
#include <cstdint>

// Problem dims: msa [1,128,256,256] f32; left_w/right_w [256,32]; out_w [1024,128]
// out [1,256,256,128] f32.
#define S_DIM 128
#define R_DIM 256
#define M_DIM 256
#define C_DIM 32
#define CZ_DIM 128
#define RC_DIM 8192          // R*C
#define CE_DIM 1024          // C*C
#define RT_DIM 65536         // R*R

// ------------------------- device scratch (no allocs allowed) -------------------------
__device__ __half gA[RC_DIM * S_DIM];            // left  [rc][s] fp16
__device__ __half gB[RC_DIM * S_DIM];            // right [te][s] fp16
__device__ __half gWt[CZ_DIM * CE_DIM];          // W^T [z][ce] fp16

// ------------------------- helpers -------------------------
__device__ __forceinline__ unsigned lds2(const unsigned short* p) {
    return *reinterpret_cast<const unsigned*>(p);
}

__device__ __forceinline__ void mma16816h(float* c, const unsigned* a, const unsigned* b) {
    asm volatile(
        "mma.sync.aligned.m16n8k16.row.col.f32.f16.f16.f32 "
        "{%0,%1,%2,%3}, {%4,%5,%6,%7}, {%8,%9}, {%0,%1,%2,%3};\n"
        : "+f"(c[0]), "+f"(c[1]), "+f"(c[2]), "+f"(c[3])
        : "r"(a[0]), "r"(a[1]), "r"(a[2]), "r"(a[3]), "r"(b[0]), "r"(b[1]));
}

__device__ __forceinline__ void cp16(void* smem, const void* g) {
    unsigned s = (unsigned)__cvta_generic_to_shared(smem);
    asm volatile("cp.async.ca.shared.global [%0], [%1], 16;\n" :: "r"(s), "l"(g));
}
#define CP_COMMIT() asm volatile("cp.async.commit_group;\n" ::: "memory")
#define CP_WAIT0()  asm volatile("cp.async.wait_group 0;\n" ::: "memory")
#define CP_WAIT1()  asm volatile("cp.async.wait_group 1;\n" ::: "memory")

// ------------------------- kernel 1: projection -------------------------
__global__ __launch_bounds__(256) void proj_kernel(const float* __restrict__ msa,
                                                   const float* __restrict__ lw,
                                                   const float* __restrict__ rw) {
    extern __shared__ float sm[];
    float* slw = sm;            // [256][32]
    float* srw = sm + 8192;     // [256][32]
    const int tid = threadIdx.x;
    for (int i = tid; i < 8192; i += 256) { slw[i] = lw[i]; srw[i] = rw[i]; }
    __syncthreads();

    const int r = blockIdx.x;
    const int w = tid >> 5, lane = tid & 31;

    for (int sg = 0; sg < 4; ++sg) {
        float v[4][8];
        int svals[4];
#pragma unroll
        for (int q = 0; q < 4; ++q) {
            int s = w + 8 * (4 * sg + q);
            svals[q] = s;
            const float* row = msa + ((size_t)(s * R_DIM + r) << 8);
#pragma unroll
            for (int i = 0; i < 8; ++i) v[q][i] = row[i * 32 + lane];
        }
        float aL[4] = {0.f, 0.f, 0.f, 0.f};
        float aR[4] = {0.f, 0.f, 0.f, 0.f};
#pragma unroll
        for (int i = 0; i < 8; ++i) {
#pragma unroll 8
            for (int j = 0; j < 32; ++j) {
                int m = i * 32 + j;
                float wl = slw[m * 32 + lane];
                float wr = srw[m * 32 + lane];
#pragma unroll
                for (int q = 0; q < 4; ++q) {
                    float x = __shfl_sync(0xffffffffu, v[q][i], j);
                    aL[q] = fmaf(x, wl, aL[q]);
                    aR[q] = fmaf(x, wr, aR[q]);
                }
            }
        }
        const int rc = r * 32 + lane;
#pragma unroll
        for (int q = 0; q < 4; ++q) {
            size_t idx = (size_t)rc * S_DIM + svals[q];
            gA[idx] = __float2half_rn(aL[q]);
            gB[idx] = __float2half_rn(aR[q]);
        }
    }
}

// ------------------------- kernel 2: W transpose -------------------------
__global__ __launch_bounds__(256) void wt_kernel(const float* __restrict__ ow) {
    int idx = blockIdx.x * 256 + threadIdx.x;     // idx = ce*128 + z
    if (idx < CE_DIM * CZ_DIM) {
        int z = idx & 127, ce = idx >> 7;
        gWt[(size_t)z * CE_DIM + ce] = __float2half_rn(ow[idx]);
    }
}

// ------------------------- kernel 3: fused GEMM1+GEMM2 -------------------------
// Per block (512 thr): phase1: A-tile [256 rows=8r x 128 s] x B-tile [128 rows=4t x 128 s]
//   -> 256x128 outer tile in regs = all 1024 ce for 32 (r,t) pairs.
// phase2: P_tile[32][1024] (fp16 smem) @ Wt[z][ce] -> out[32][128], ce-chunked 128,
//   W chunks double-buffered via cp.async.
#define WST 136          // 128 + 8 pad (272B rows)
#define PT_STRIDE 1032   // 1024 + 8 pad (2064B rows; banks g*4 -> conflict-free)
#define SM_W0 0                          // W bufs: 2 x 128 x WST
#define SM_A  (2 * 128 * WST)            // A: 256 x WST
#define SM_B  (SM_A + 256 * WST)         // B: 128 x WST
#define SM_P  SM_A                       // P tile overlays A region (32x1032 <= 256x136)
#define FUSED_SMEM ((SM_B + 128 * WST) * 2)   // ushort count *2 bytes = 174080

__global__ __launch_bounds__(512) void fused_kernel(float* __restrict__ out) {
    extern __shared__ unsigned short sm16[];
    unsigned short* sW = sm16 + SM_W0;
    unsigned short* sA = sm16 + SM_A;
    unsigned short* sB = sm16 + SM_B;
    unsigned short* sP = sm16 + SM_P;

    const int tid = threadIdx.x;
    const int tb = blockIdx.x;           // 0..63  (4 t per block)
    const int rb = blockIdx.y;           // 0..31  (8 r per block)
    const size_t mb = (size_t)rb * 256;  // gA row base
    const size_t nb = (size_t)tb * 128;  // gB row base

    // ---- issue A+B tile loads (group 0) ----
#pragma unroll
    for (int i = 0; i < 8; ++i) {
        int idx = tid * 8 + i;                    // 4096 vectors
        int row = idx >> 4, c16 = idx & 15;
        cp16(sA + row * WST + c16 * 8,
             (const __half*)gA + (mb + row) * S_DIM + c16 * 8);
    }
#pragma unroll
    for (int i = 0; i < 4; ++i) {
        int idx = tid * 4 + i;                    // 2048 vectors
        int row = idx >> 4, c16 = idx & 15;
        cp16(sB + row * WST + c16 * 8,
             (const __half*)gB + (nb + row) * S_DIM + c16 * 8);
    }
    CP_COMMIT();
    // ---- prefetch W chunk 0 into buf 0 (group 1) ----
#pragma unroll
    for (int i = 0; i < 4; ++i) {
        int idx = tid * 4 + i;                    // 2048 vectors
        int z = idx >> 4, c16 = idx & 15;
        cp16(sW + z * WST + c16 * 8, (const __half*)gWt + (size_t)z * CE_DIM + c16 * 8);
    }
    CP_COMMIT();
    CP_WAIT1();   // A+B ready; W0 may still be in flight
    __syncthreads();

    const int wid = tid >> 5, lane = tid & 31;
    const int g = lane >> 2, tg2 = (lane & 3) * 2;

    // ---- phase 1: 256x128 outer tile, K = 128 ----
    const int wm0 = (wid & 3) * 64, wn0 = (wid >> 2) * 32;
    float acc[4][4][4];
#pragma unroll
    for (int mi = 0; mi < 4; ++mi)
#pragma unroll
        for (int nj = 0; nj < 4; ++nj)
#pragma unroll
            for (int k = 0; k < 4; ++k) acc[mi][nj][k] = 0.f;

#pragma unroll
    for (int ks = 0; ks < 128; ks += 16) {
        unsigned a[4][4], b[4][2];
#pragma unroll
        for (int mi = 0; mi < 4; ++mi) {
            int base = (wm0 + mi * 16 + g) * WST + ks + tg2;
            a[mi][0] = lds2(sA + base);
            a[mi][1] = lds2(sA + base + 8 * WST);
            a[mi][2] = lds2(sA + base + 8);
            a[mi][3] = lds2(sA + base + 8 * WST + 8);
        }
#pragma unroll
        for (int nj = 0; nj < 4; ++nj) {
            int base = (wn0 + nj * 8 + g) * WST + ks + tg2;
            b[nj][0] = lds2(sB + base);
            b[nj][1] = lds2(sB + base + 8);
        }
#pragma unroll
        for (int mi = 0; mi < 4; ++mi)
#pragma unroll
            for (int nj = 0; nj < 4; ++nj)
                mma16816h(acc[mi][nj], a[mi], b[nj]);
    }
    __syncthreads();   // all reads of sA/sB done before P overlay

    // ---- store P tile (fp16) into smem: row rt_local = r_local*4+t_local, col c*32+e ----
#pragma unroll
    for (int mi = 0; mi < 4; ++mi) {
#pragma unroll
        for (int nj = 0; nj < 4; ++nj) {
            int n = wn0 + nj * 8 + tg2;
            int t_local = n >> 5, e = n & 31;
#pragma unroll
            for (int half = 0; half < 2; ++half) {
                int m = wm0 + mi * 16 + g + half * 8;
                int r_local = m >> 5, c = m & 31;
                int rtl = r_local * 4 + t_local;
                __half h0 = __float2half_rn(acc[mi][nj][half * 2 + 0]);
                __half h1 = __float2half_rn(acc[mi][nj][half * 2 + 1]);
                unsigned hp = (unsigned)__half_as_ushort(h0) |
                              ((unsigned)__half_as_ushort(h1) << 16);
                *(unsigned*)(sP + rtl * PT_STRIDE + c * 32 + e) = hp;
            }
        }
    }
    __syncthreads();

    // ---- phase 2: P_tile[32][1024] @ Wt -> out[32][128], 8 ce-chunks of 128 ----
    const int m16 = (wid & 1) * 16;       // P rows 0-15 / 16-31
    const int n0 = (wid >> 1) * 16;       // two n8 tiles: n0, n0+8
    float acc2[2][4] = {{0.f, 0.f, 0.f, 0.f}, {0.f, 0.f, 0.f, 0.f}};

    for (int kci = 0; kci < 8; ++kci) {
        const int cur = kci & 1;
        if (kci + 1 < 8) {
            unsigned short* sWn = sW + (cur ^ 1) * 128 * WST;
            const size_t kc = (size_t)(kci + 1) * 128;
#pragma unroll
            for (int i = 0; i < 4; ++i) {
                int idx = tid * 4 + i;
                int z = idx >> 4, c16 = idx & 15;
                cp16(sWn + z * WST + c16 * 8,
                     (const __half*)gWt + (size_t)z * CE_DIM + kc + c16 * 8);
            }
            CP_COMMIT();
            CP_WAIT1();
        } else {
            CP_WAIT0();
        }
        __syncthreads();

        unsigned short* sWc = sW + cur * 128 * WST;
        const int ccol = kci * 128;
#pragma unroll
        for (int ks = 0; ks < 128; ks += 16) {
            unsigned a[4], b[2][2];
            int abase = (m16 + g) * PT_STRIDE + ccol + ks + tg2;
            a[0] = lds2(sP + abase);
            a[1] = lds2(sP + abase + 8 * PT_STRIDE);
            a[2] = lds2(sP + abase + 8);
            a[3] = lds2(sP + abase + 8 * PT_STRIDE + 8);
#pragma unroll
            for (int j = 0; j < 2; ++j) {
                int bbase = (n0 + j * 8 + g) * WST + ks + tg2;
                b[j][0] = lds2(sWc + bbase);
                b[j][1] = lds2(sWc + bbase + 8);
            }
            mma16816h(acc2[0], a, b[0]);
            mma16816h(acc2[1], a, b[1]);
        }
        __syncthreads();
    }

    // ---- epilogue: out[(rb*8+r_local)*256 + tb*4 + t_local][z], coalesced float2 ----
#pragma unroll
    for (int j = 0; j < 2; ++j) {
        int z = n0 + j * 8 + tg2;
#pragma unroll
        for (int half = 0; half < 2; ++half) {
            int rtl = m16 + g + half * 8;
            int r_local = rtl >> 2, t_local = rtl & 3;
            size_t row = (((size_t)(rb * 8 + r_local)) << 8) + tb * 4 + t_local;
            float2 v;
            v.x = acc2[j][half * 2 + 0];
            v.y = acc2[j][half * 2 + 1];
            *(float2*)(out + row * CZ_DIM + z) = v;
        }
    }
}

// ------------------------- launch -------------------------
extern "C" void kernel_launch(void* const* d_in, const int* in_sizes, int n_in,
                              void* d_out, int out_size) {
    const float* msa = (const float*)d_in[0];
    const float* lw  = (const float*)d_in[1];
    const float* rw  = (const float*)d_in[2];
    const float* ow  = (const float*)d_in[3];
    float* out = (float*)d_out;

    (void)in_sizes; (void)n_in; (void)out_size;

    const int proj_smem  = 2 * 8192 * (int)sizeof(float);   // 64 KB
    const int fused_smem = FUSED_SMEM;                      // 174080 B

    cudaFuncSetAttribute((const void*)proj_kernel,
                         cudaFuncAttributeMaxDynamicSharedMemorySize, proj_smem);
    cudaFuncSetAttribute((const void*)fused_kernel,
                         cudaFuncAttributeMaxDynamicSharedMemorySize, fused_smem);

    proj_kernel<<<R_DIM, 256, proj_smem>>>(msa, lw, rw);
    wt_kernel<<<(CE_DIM * CZ_DIM + 255) / 256, 256>>>(ow);
    fused_kernel<<<dim3(64, 32), 512, fused_smem>>>(out);
}

// round 8
// speedup vs baseline: 1.5645x; 1.5645x over previous
#include <cuda_runtime.h>
#include <cuda_fp16.h>
#include <cuda_bf16.h>
#include <cstdint>

// Problem dims: msa [1,128,256,256] f32; left_w/right_w [256,32]; out_w [1024,128]
// out [1,256,256,128] f32.
#define S_DIM 128
#define R_DIM 256
#define M_DIM 256
#define C_DIM 32
#define CZ_DIM 128
#define RC_DIM 8192          // R*C
#define CE_DIM 1024          // C*C
#define RT_DIM 65536         // R*R

// ------------------------- device scratch (no allocs allowed) -------------------------
__device__ __half gA[RC_DIM * S_DIM];                 // left  [rc][s] fp16
__device__ __half gB[RC_DIM * S_DIM];                 // right [te][s] fp16
__device__ __half gP[(size_t)RT_DIM * CE_DIM];        // P [rt][ce] fp16
__device__ __half gWt[CZ_DIM * CE_DIM];               // W^T [z][ce] fp16 (gemm2)
__device__ unsigned short gWph[64 * M_DIM];           // proj weights hi [n][m] bf16
__device__ unsigned short gWpl[64 * M_DIM];           // proj weights lo [n][m] bf16

// ------------------------- helpers -------------------------
__device__ __forceinline__ unsigned lds2(const unsigned short* p) {
    return *reinterpret_cast<const unsigned*>(p);
}

__device__ __forceinline__ void mma16816h(float* c, const unsigned* a, const unsigned* b) {
    asm volatile(
        "mma.sync.aligned.m16n8k16.row.col.f32.f16.f16.f32 "
        "{%0,%1,%2,%3}, {%4,%5,%6,%7}, {%8,%9}, {%0,%1,%2,%3};\n"
        : "+f"(c[0]), "+f"(c[1]), "+f"(c[2]), "+f"(c[3])
        : "r"(a[0]), "r"(a[1]), "r"(a[2]), "r"(a[3]), "r"(b[0]), "r"(b[1]));
}

__device__ __forceinline__ void mma16816bf(float* c, const unsigned* a, const unsigned* b) {
    asm volatile(
        "mma.sync.aligned.m16n8k16.row.col.f32.bf16.bf16.f32 "
        "{%0,%1,%2,%3}, {%4,%5,%6,%7}, {%8,%9}, {%0,%1,%2,%3};\n"
        : "+f"(c[0]), "+f"(c[1]), "+f"(c[2]), "+f"(c[3])
        : "r"(a[0]), "r"(a[1]), "r"(a[2]), "r"(a[3]), "r"(b[0]), "r"(b[1]));
}

__device__ __forceinline__ void cp16(void* smem, const void* g) {
    unsigned s = (unsigned)__cvta_generic_to_shared(smem);
    asm volatile("cp.async.ca.shared.global [%0], [%1], 16;\n" :: "r"(s), "l"(g));
}
#define CP_COMMIT() asm volatile("cp.async.commit_group;\n" ::: "memory")
#define CP_WAIT0()  asm volatile("cp.async.wait_group 0;\n" ::: "memory")
#define CP_WAIT1()  asm volatile("cp.async.wait_group 1;\n" ::: "memory")

__device__ __forceinline__ void bf_split(float x, unsigned short& h, unsigned short& l) {
    __nv_bfloat16 hb = __float2bfloat16_rn(x);
    h = *reinterpret_cast<unsigned short*>(&hb);
    __nv_bfloat16 lb = __float2bfloat16_rn(x - __bfloat162float(hb));
    l = *reinterpret_cast<unsigned short*>(&lb);
}

// ------------------------- kernel 0: weight prep -------------------------
// gWp[n][m]: n<32 -> left_w[m][n]; n>=32 -> right_w[m][n-32]  (bf16 split)
// gWt[z][ce] = out_w[ce][z]  (fp16)
__global__ __launch_bounds__(256) void prep_kernel(const float* __restrict__ lw,
                                                   const float* __restrict__ rw,
                                                   const float* __restrict__ ow) {
    int idx = blockIdx.x * 256 + threadIdx.x;
    if (idx < 64 * M_DIM) {
        int n = idx >> 8, m = idx & 255;
        float x = (n < 32) ? lw[m * 32 + n] : rw[m * 32 + (n - 32)];
        unsigned short h, l;
        bf_split(x, h, l);
        gWph[n * M_DIM + m] = h;
        gWpl[n * M_DIM + m] = l;
    }
    if (idx < CE_DIM * CZ_DIM) {     // idx = ce*128 + z
        int z = idx & 127, ce = idx >> 7;
        gWt[(size_t)z * CE_DIM + ce] = __float2half_rn(ow[idx]);
    }
}

// ------------------------- kernel 1: projection (tensor cores) -------------------------
// Per block (one r): [128 s x 256 m] @ [m x 64 cols] via 3-term bf16 split MMA.
// Epilogue transposes to gA[(r*32+c)][s], gB likewise (coalesced 256B rows).
#define PWS 264          // 256 + 8 pad
#define P_SWH 0
#define P_SWL (64 * PWS)
#define P_SAH (2 * 64 * PWS)
#define P_SAL (P_SAH + 128 * PWS)
#define PROJ_SMEM ((P_SAL + 128 * PWS) * 2)   // 202752 B
__global__ __launch_bounds__(256) void proj_tc_kernel(const float* __restrict__ msa) {
    extern __shared__ unsigned short sm16[];
    unsigned short* sWh = sm16 + P_SWH;
    unsigned short* sWl = sm16 + P_SWL;
    unsigned short* sAh = sm16 + P_SAH;
    unsigned short* sAl = sm16 + P_SAL;
    unsigned short* sT  = sm16 + P_SAH;    // transpose overlay (8704 ush)

    const int tid = threadIdx.x;
    const int r = blockIdx.x;

    // weights via cp.async: 2 planes x 2048 vecs
#pragma unroll
    for (int i = 0; i < 16; ++i) {
        int idx = tid + 256 * i;
        int plane = idx >> 11, rem = idx & 2047;
        int n = rem >> 5, seg = rem & 31;
        unsigned short* dst = (plane ? sWl : sWh) + n * PWS + seg * 8;
        const unsigned short* src = (plane ? gWpl : gWph) + n * M_DIM + seg * 8;
        cp16(dst, src);
    }
    CP_COMMIT();

    // msa rows: load f32, split to bf16 hi/lo in smem
#pragma unroll
    for (int i = 0; i < 32; ++i) {
        int v = tid + 256 * i;
        int row = v >> 6, col4 = v & 63;
        const float4 x = *(const float4*)(msa + (((size_t)(row * R_DIM + r)) << 8) + col4 * 4);
        unsigned short h0, h1, h2, h3, l0, l1, l2, l3;
        bf_split(x.x, h0, l0); bf_split(x.y, h1, l1);
        bf_split(x.z, h2, l2); bf_split(x.w, h3, l3);
        int ofs = row * PWS + col4 * 4;
        *(unsigned*)(sAh + ofs)     = (unsigned)h0 | ((unsigned)h1 << 16);
        *(unsigned*)(sAh + ofs + 2) = (unsigned)h2 | ((unsigned)h3 << 16);
        *(unsigned*)(sAl + ofs)     = (unsigned)l0 | ((unsigned)l1 << 16);
        *(unsigned*)(sAl + ofs + 2) = (unsigned)l2 | ((unsigned)l3 << 16);
    }
    CP_WAIT0();
    __syncthreads();

    const int wid = tid >> 5, lane = tid & 31;
    const int g = lane >> 2, tg2 = (lane & 3) * 2;
    const int wm0 = (wid & 3) * 32, wn0 = (wid >> 2) * 32;

    float acc[2][4][4];
#pragma unroll
    for (int mi = 0; mi < 2; ++mi)
#pragma unroll
        for (int nj = 0; nj < 4; ++nj)
#pragma unroll
            for (int k = 0; k < 4; ++k) acc[mi][nj][k] = 0.f;

#pragma unroll
    for (int ks = 0; ks < 256; ks += 16) {
        unsigned ah[2][4], al[2][4], bh[4][2], bl[4][2];
#pragma unroll
        for (int mi = 0; mi < 2; ++mi) {
            int base = (wm0 + mi * 16 + g) * PWS + ks + tg2;
            ah[mi][0] = lds2(sAh + base);
            ah[mi][1] = lds2(sAh + base + 8 * PWS);
            ah[mi][2] = lds2(sAh + base + 8);
            ah[mi][3] = lds2(sAh + base + 8 * PWS + 8);
            al[mi][0] = lds2(sAl + base);
            al[mi][1] = lds2(sAl + base + 8 * PWS);
            al[mi][2] = lds2(sAl + base + 8);
            al[mi][3] = lds2(sAl + base + 8 * PWS + 8);
        }
#pragma unroll
        for (int nj = 0; nj < 4; ++nj) {
            int base = (wn0 + nj * 8 + g) * PWS + ks + tg2;
            bh[nj][0] = lds2(sWh + base);
            bh[nj][1] = lds2(sWh + base + 8);
            bl[nj][0] = lds2(sWl + base);
            bl[nj][1] = lds2(sWl + base + 8);
        }
#pragma unroll
        for (int mi = 0; mi < 2; ++mi)
#pragma unroll
            for (int nj = 0; nj < 4; ++nj) {
                mma16816bf(acc[mi][nj], ah[mi], bh[nj]);
                mma16816bf(acc[mi][nj], ah[mi], bl[nj]);
                mma16816bf(acc[mi][nj], al[mi], bh[nj]);
            }
    }
    __syncthreads();   // done reading sAh/sAl before overlay

    // transpose: sT[col * 136 + s] fp16
#pragma unroll
    for (int mi = 0; mi < 2; ++mi)
#pragma unroll
        for (int nj = 0; nj < 4; ++nj)
#pragma unroll
            for (int half = 0; half < 2; ++half)
#pragma unroll
                for (int q = 0; q < 2; ++q) {
                    int n = wn0 + nj * 8 + tg2 + q;
                    int s = wm0 + mi * 16 + g + half * 8;
                    __half v = __float2half_rn(acc[mi][nj][half * 2 + q]);
                    sT[n * 136 + s] = *reinterpret_cast<unsigned short*>(&v);
                }
    __syncthreads();

    // coalesced copy out: 64 rows x 256B
#pragma unroll
    for (int i = 0; i < 4; ++i) {
        int v = tid + 256 * i;
        int col = v >> 4, seg = v & 15;
        uint4 d = *(uint4*)(sT + col * 136 + seg * 8);
        __half* dst = (col < 32)
            ? (__half*)gA + (((size_t)r * 32 + col) * S_DIM) + seg * 8
            : (__half*)gB + (((size_t)r * 32 + col - 32) * S_DIM) + seg * 8;
        *(uint4*)dst = d;
    }
}

// ------------------------- kernel 2: GEMM1 -------------------------
// P[(r,c),(t,e)] = sum_s A[rc][s] * B[te][s].  Block 128x128, K=128 as 2x64
// double-buffered cp.async stages; epilogue staged in smem -> coalesced 2KB rows.
#define G1S 72                        // 64 + 8 pad
#define G1_PLANE (128 * G1S)
#define G1_SMEM (4 * G1_PLANE * 2)    // 73728 B
#define PE_STRIDE 1032
__global__ __launch_bounds__(256, 2) void gemm1_kernel() {
    extern __shared__ unsigned short sm16[];
    unsigned short* sE = sm16;        // epilogue overlay: 16 x 1032

    const int tid = threadIdx.x;
    const int mb = blockIdx.y * 128, nb = blockIdx.x * 128;

    auto issue = [&](int st, int kc) {
        unsigned short* sA = sm16 + st * G1_PLANE;
        unsigned short* sB = sm16 + 2 * G1_PLANE + st * G1_PLANE;
#pragma unroll
        for (int i = 0; i < 4; ++i) {
            int idx = tid * 4 + i;
            int row = idx >> 3, seg = idx & 7;
            cp16(sA + row * G1S + seg * 8,
                 (const __half*)gA + (size_t)(mb + row) * S_DIM + kc + seg * 8);
            cp16(sB + row * G1S + seg * 8,
                 (const __half*)gB + (size_t)(nb + row) * S_DIM + kc + seg * 8);
        }
        CP_COMMIT();
    };

    issue(0, 0);
    issue(1, 64);

    const int wid = tid >> 5, lane = tid & 31;
    const int wm0 = (wid & 1) * 64, wn0 = (wid >> 1) * 32;
    const int g = lane >> 2, tg2 = (lane & 3) * 2;

    float acc[4][4][4];
#pragma unroll
    for (int mi = 0; mi < 4; ++mi)
#pragma unroll
        for (int nj = 0; nj < 4; ++nj)
#pragma unroll
            for (int k = 0; k < 4; ++k) acc[mi][nj][k] = 0.f;

    CP_WAIT1();
    __syncthreads();

#pragma unroll
    for (int st = 0; st < 2; ++st) {
        unsigned short* sA = sm16 + st * G1_PLANE;
        unsigned short* sB = sm16 + 2 * G1_PLANE + st * G1_PLANE;
#pragma unroll
        for (int ks = 0; ks < 64; ks += 16) {
            unsigned a[4][4], b[4][2];
#pragma unroll
            for (int mi = 0; mi < 4; ++mi) {
                int base = (wm0 + mi * 16 + g) * G1S + ks + tg2;
                a[mi][0] = lds2(sA + base);
                a[mi][1] = lds2(sA + base + 8 * G1S);
                a[mi][2] = lds2(sA + base + 8);
                a[mi][3] = lds2(sA + base + 8 * G1S + 8);
            }
#pragma unroll
            for (int nj = 0; nj < 4; ++nj) {
                int base = (wn0 + nj * 8 + g) * G1S + ks + tg2;
                b[nj][0] = lds2(sB + base);
                b[nj][1] = lds2(sB + base + 8);
            }
#pragma unroll
            for (int mi = 0; mi < 4; ++mi)
#pragma unroll
                for (int nj = 0; nj < 4; ++nj)
                    mma16816h(acc[mi][nj], a[mi], b[nj]);
        }
        if (st == 0) {
            CP_WAIT0();
            __syncthreads();
        }
    }
    __syncthreads();   // all tile reads done before epilogue overlay

    // stage P tile: sE[rtl][c*32+e], rtl = r_local*4 + t_local
#pragma unroll
    for (int mi = 0; mi < 4; ++mi) {
#pragma unroll
        for (int nj = 0; nj < 4; ++nj) {
            int n = wn0 + nj * 8 + tg2;
            int t_local = n >> 5, e = n & 31;
#pragma unroll
            for (int half = 0; half < 2; ++half) {
                int m = wm0 + mi * 16 + g + half * 8;
                int r_local = m >> 5, c = m & 31;
                int rtl = r_local * 4 + t_local;
                __half h0 = __float2half_rn(acc[mi][nj][half * 2 + 0]);
                __half h1 = __float2half_rn(acc[mi][nj][half * 2 + 1]);
                unsigned hp = (unsigned)__half_as_ushort(h0) |
                              ((unsigned)__half_as_ushort(h1) << 16);
                *(unsigned*)(sE + rtl * PE_STRIDE + c * 32 + e) = hp;
            }
        }
    }
    __syncthreads();

    // coalesced write: 16 complete P rows of 2KB
    const int r_base = blockIdx.y * 4, t_base = blockIdx.x * 4;
#pragma unroll
    for (int i = 0; i < 8; ++i) {
        int v = tid + 256 * i;
        int row = v >> 7, seg = v & 127;
        uint4 d = *(uint4*)(sE + row * PE_STRIDE + seg * 8);
        size_t rt = (((size_t)(r_base + (row >> 2))) << 8) + t_base + (row & 3);
        *(uint4*)((__half*)gP + rt * CE_DIM + seg * 8) = d;
    }
}

// ------------------------- kernel 3: GEMM2 -------------------------
// out[(r,t),z] = sum_ce P[rt][ce] * Wt[z][ce]. M=65536, N=128, K=1024.
// Block 128x128, K-chunk 64, cp.async double-buffered.
#define G2_STRIDE 72
#define G2_PLANE  (128 * G2_STRIDE)
__global__ __launch_bounds__(256, 2) void gemm2_kernel(float* __restrict__ out) {
    extern __shared__ unsigned short sm16[];
    unsigned short* sbuf = sm16;

    const int tid = threadIdx.x;
    const size_t mb = (size_t)blockIdx.x * 128;
    const int wid = tid >> 5, lane = tid & 31;
    const int wm0 = (wid & 1) * 64, wn0 = (wid >> 1) * 32;
    const int g = lane >> 2, tg2 = (lane & 3) * 2;

    auto issue = [&](int st, int kc) {
        unsigned short* sA = sbuf + st * 2 * G2_PLANE;
        unsigned short* sB = sA + G2_PLANE;
#pragma unroll
        for (int i = 0; i < 4; ++i) {
            int idx = tid * 4 + i;
            int row = idx >> 3, seg = idx & 7;
            const int sofs = row * G2_STRIDE + seg * 8;
            cp16(sA + sofs, (const __half*)gP + (mb + row) * CE_DIM + kc + seg * 8);
            cp16(sB + sofs, (const __half*)gWt + (size_t)row * CE_DIM + kc + seg * 8);
        }
        CP_COMMIT();
    };

    float acc[4][4][4];
#pragma unroll
    for (int mi = 0; mi < 4; ++mi)
#pragma unroll
        for (int nj = 0; nj < 4; ++nj)
#pragma unroll
            for (int k = 0; k < 4; ++k) acc[mi][nj][k] = 0.f;

    issue(0, 0);

    for (int kci = 0; kci < 16; ++kci) {
        const int cur = kci & 1;
        if (kci + 1 < 16) {
            issue(cur ^ 1, (kci + 1) * 64);
            CP_WAIT1();
        } else {
            CP_WAIT0();
        }
        __syncthreads();

        unsigned short* sA = sbuf + cur * 2 * G2_PLANE;
        unsigned short* sB = sA + G2_PLANE;
#pragma unroll
        for (int ks = 0; ks < 64; ks += 16) {
            unsigned a[4][4], b[4][2];
#pragma unroll
            for (int mi = 0; mi < 4; ++mi) {
                int base = (wm0 + mi * 16 + g) * G2_STRIDE + ks + tg2;
                a[mi][0] = lds2(sA + base);
                a[mi][1] = lds2(sA + base + 8 * G2_STRIDE);
                a[mi][2] = lds2(sA + base + 8);
                a[mi][3] = lds2(sA + base + 8 * G2_STRIDE + 8);
            }
#pragma unroll
            for (int nj = 0; nj < 4; ++nj) {
                int base = (wn0 + nj * 8 + g) * G2_STRIDE + ks + tg2;
                b[nj][0] = lds2(sB + base);
                b[nj][1] = lds2(sB + base + 8);
            }
#pragma unroll
            for (int mi = 0; mi < 4; ++mi)
#pragma unroll
                for (int nj = 0; nj < 4; ++nj)
                    mma16816h(acc[mi][nj], a[mi], b[nj]);
        }
        __syncthreads();
    }

#pragma unroll
    for (int mi = 0; mi < 4; ++mi) {
#pragma unroll
        for (int nj = 0; nj < 4; ++nj) {
            int n = wn0 + nj * 8 + tg2;
#pragma unroll
            for (int half = 0; half < 2; ++half) {
                size_t m = mb + wm0 + mi * 16 + g + half * 8;
                float2 v;
                v.x = acc[mi][nj][half * 2 + 0];
                v.y = acc[mi][nj][half * 2 + 1];
                *(float2*)(out + m * CZ_DIM + n) = v;
            }
        }
    }
}

// ------------------------- launch -------------------------
extern "C" void kernel_launch(void* const* d_in, const int* in_sizes, int n_in,
                              void* d_out, int out_size) {
    const float* msa = (const float*)d_in[0];
    const float* lw  = (const float*)d_in[1];
    const float* rw  = (const float*)d_in[2];
    const float* ow  = (const float*)d_in[3];
    float* out = (float*)d_out;

    (void)in_sizes; (void)n_in; (void)out_size;

    const int g2_smem = 2 * 2 * G2_PLANE * 2;   // 73728 B

    cudaFuncSetAttribute((const void*)proj_tc_kernel,
                         cudaFuncAttributeMaxDynamicSharedMemorySize, PROJ_SMEM);
    cudaFuncSetAttribute((const void*)gemm1_kernel,
                         cudaFuncAttributeMaxDynamicSharedMemorySize, G1_SMEM);
    cudaFuncSetAttribute((const void*)gemm2_kernel,
                         cudaFuncAttributeMaxDynamicSharedMemorySize, g2_smem);

    prep_kernel<<<(CE_DIM * CZ_DIM + 255) / 256, 256>>>(lw, rw, ow);
    proj_tc_kernel<<<R_DIM, 256, PROJ_SMEM>>>(msa);
    gemm1_kernel<<<dim3(64, 64), 256, G1_SMEM>>>();
    gemm2_kernel<<<RT_DIM / 128, 256, g2_smem>>>(out);
}

// round 10
// speedup vs baseline: 1.8115x; 1.1579x over previous
#include <cuda_runtime.h>
#include <cuda_fp16.h>
#include <cuda_bf16.h>
#include <cstdint>

// Problem dims: msa [1,128,256,256] f32; left_w/right_w [256,32]; out_w [1024,128]
// out [1,256,256,128] f32.
#define S_DIM 128
#define R_DIM 256
#define M_DIM 256
#define C_DIM 32
#define CZ_DIM 128
#define RC_DIM 8192          // R*C
#define CE_DIM 1024          // C*C
#define RT_DIM 65536         // R*R

// ------------------------- device scratch (no allocs allowed) -------------------------
__device__ __half gA[RC_DIM * S_DIM];                 // left  [rc][s] fp16
__device__ __half gB[RC_DIM * S_DIM];                 // right [te][s] fp16
__device__ __half gP[(size_t)RT_DIM * CE_DIM];        // P [rt][ce] fp16
__device__ __half gWt[CZ_DIM * CE_DIM];               // W^T [z][ce] fp16 (gemm2)
__device__ unsigned short gWph[64 * M_DIM];           // proj weights hi [n][m] bf16
__device__ unsigned short gWpl[64 * M_DIM];           // proj weights lo [n][m] bf16

// ------------------------- helpers -------------------------
__device__ __forceinline__ unsigned lds2(const unsigned short* p) {
    return *reinterpret_cast<const unsigned*>(p);
}

__device__ __forceinline__ void mma16816h(float* c, const unsigned* a, const unsigned* b) {
    asm volatile(
        "mma.sync.aligned.m16n8k16.row.col.f32.f16.f16.f32 "
        "{%0,%1,%2,%3}, {%4,%5,%6,%7}, {%8,%9}, {%0,%1,%2,%3};\n"
        : "+f"(c[0]), "+f"(c[1]), "+f"(c[2]), "+f"(c[3])
        : "r"(a[0]), "r"(a[1]), "r"(a[2]), "r"(a[3]), "r"(b[0]), "r"(b[1]));
}

__device__ __forceinline__ void mma16816bf(float* c, const unsigned* a, const unsigned* b) {
    asm volatile(
        "mma.sync.aligned.m16n8k16.row.col.f32.bf16.bf16.f32 "
        "{%0,%1,%2,%3}, {%4,%5,%6,%7}, {%8,%9}, {%0,%1,%2,%3};\n"
        : "+f"(c[0]), "+f"(c[1]), "+f"(c[2]), "+f"(c[3])
        : "r"(a[0]), "r"(a[1]), "r"(a[2]), "r"(a[3]), "r"(b[0]), "r"(b[1]));
}

__device__ __forceinline__ void cp16(void* smem, const void* g) {
    unsigned s = (unsigned)__cvta_generic_to_shared(smem);
    asm volatile("cp.async.ca.shared.global [%0], [%1], 16;\n" :: "r"(s), "l"(g));
}
#define CP_COMMIT() asm volatile("cp.async.commit_group;\n" ::: "memory")
#define CP_WAIT0()  asm volatile("cp.async.wait_group 0;\n" ::: "memory")
#define CP_WAIT1()  asm volatile("cp.async.wait_group 1;\n" ::: "memory")

__device__ __forceinline__ void bf_split(float x, unsigned short& h, unsigned short& l) {
    __nv_bfloat16 hb = __float2bfloat16_rn(x);
    h = *reinterpret_cast<unsigned short*>(&hb);
    __nv_bfloat16 lb = __float2bfloat16_rn(x - __bfloat162float(hb));
    l = *reinterpret_cast<unsigned short*>(&lb);
}

// ------------------------- kernel 0: weight prep -------------------------
__global__ __launch_bounds__(256) void prep_kernel(const float* __restrict__ lw,
                                                   const float* __restrict__ rw,
                                                   const float* __restrict__ ow) {
    int idx = blockIdx.x * 256 + threadIdx.x;
    if (idx < 64 * M_DIM) {
        int n = idx >> 8, m = idx & 255;
        float x = (n < 32) ? lw[m * 32 + n] : rw[m * 32 + (n - 32)];
        unsigned short h, l;
        bf_split(x, h, l);
        gWph[n * M_DIM + m] = h;
        gWpl[n * M_DIM + m] = l;
    }
    if (idx < CE_DIM * CZ_DIM) {     // idx = ce*128 + z
        int z = idx & 127, ce = idx >> 7;
        gWt[(size_t)z * CE_DIM + ce] = __float2half_rn(ow[idx]);
    }
}

// ------------------------- kernel 1: projection (tensor cores) -------------------------
#define PWS 264          // 256 + 8 pad
#define P_SWH 0
#define P_SWL (64 * PWS)
#define P_SAH (2 * 64 * PWS)
#define P_SAL (P_SAH + 128 * PWS)
#define PROJ_SMEM ((P_SAL + 128 * PWS) * 2)   // 202752 B
__global__ __launch_bounds__(256) void proj_tc_kernel(const float* __restrict__ msa) {
    extern __shared__ unsigned short sm16[];
    unsigned short* sWh = sm16 + P_SWH;
    unsigned short* sWl = sm16 + P_SWL;
    unsigned short* sAh = sm16 + P_SAH;
    unsigned short* sAl = sm16 + P_SAL;
    unsigned short* sT  = sm16 + P_SAH;

    const int tid = threadIdx.x;
    const int r = blockIdx.x;

#pragma unroll
    for (int i = 0; i < 16; ++i) {
        int idx = tid + 256 * i;
        int plane = idx >> 11, rem = idx & 2047;
        int n = rem >> 5, seg = rem & 31;
        unsigned short* dst = (plane ? sWl : sWh) + n * PWS + seg * 8;
        const unsigned short* src = (plane ? gWpl : gWph) + n * M_DIM + seg * 8;
        cp16(dst, src);
    }
    CP_COMMIT();

#pragma unroll
    for (int i = 0; i < 32; ++i) {
        int v = tid + 256 * i;
        int row = v >> 6, col4 = v & 63;
        const float4 x = *(const float4*)(msa + (((size_t)(row * R_DIM + r)) << 8) + col4 * 4);
        unsigned short h0, h1, h2, h3, l0, l1, l2, l3;
        bf_split(x.x, h0, l0); bf_split(x.y, h1, l1);
        bf_split(x.z, h2, l2); bf_split(x.w, h3, l3);
        int ofs = row * PWS + col4 * 4;
        *(unsigned*)(sAh + ofs)     = (unsigned)h0 | ((unsigned)h1 << 16);
        *(unsigned*)(sAh + ofs + 2) = (unsigned)h2 | ((unsigned)h3 << 16);
        *(unsigned*)(sAl + ofs)     = (unsigned)l0 | ((unsigned)l1 << 16);
        *(unsigned*)(sAl + ofs + 2) = (unsigned)l2 | ((unsigned)l3 << 16);
    }
    CP_WAIT0();
    __syncthreads();

    const int wid = tid >> 5, lane = tid & 31;
    const int g = lane >> 2, tg2 = (lane & 3) * 2;
    const int wm0 = (wid & 3) * 32, wn0 = (wid >> 2) * 32;

    float acc[2][4][4];
#pragma unroll
    for (int mi = 0; mi < 2; ++mi)
#pragma unroll
        for (int nj = 0; nj < 4; ++nj)
#pragma unroll
            for (int k = 0; k < 4; ++k) acc[mi][nj][k] = 0.f;

#pragma unroll
    for (int ks = 0; ks < 256; ks += 16) {
        unsigned ah[2][4], al[2][4], bh[4][2], bl[4][2];
#pragma unroll
        for (int mi = 0; mi < 2; ++mi) {
            int base = (wm0 + mi * 16 + g) * PWS + ks + tg2;
            ah[mi][0] = lds2(sAh + base);
            ah[mi][1] = lds2(sAh + base + 8 * PWS);
            ah[mi][2] = lds2(sAh + base + 8);
            ah[mi][3] = lds2(sAh + base + 8 * PWS + 8);
            al[mi][0] = lds2(sAl + base);
            al[mi][1] = lds2(sAl + base + 8 * PWS);
            al[mi][2] = lds2(sAl + base + 8);
            al[mi][3] = lds2(sAl + base + 8 * PWS + 8);
        }
#pragma unroll
        for (int nj = 0; nj < 4; ++nj) {
            int base = (wn0 + nj * 8 + g) * PWS + ks + tg2;
            bh[nj][0] = lds2(sWh + base);
            bh[nj][1] = lds2(sWh + base + 8);
            bl[nj][0] = lds2(sWl + base);
            bl[nj][1] = lds2(sWl + base + 8);
        }
#pragma unroll
        for (int mi = 0; mi < 2; ++mi)
#pragma unroll
            for (int nj = 0; nj < 4; ++nj) {
                mma16816bf(acc[mi][nj], ah[mi], bh[nj]);
                mma16816bf(acc[mi][nj], ah[mi], bl[nj]);
                mma16816bf(acc[mi][nj], al[mi], bh[nj]);
            }
    }
    __syncthreads();

#pragma unroll
    for (int mi = 0; mi < 2; ++mi)
#pragma unroll
        for (int nj = 0; nj < 4; ++nj)
#pragma unroll
            for (int half = 0; half < 2; ++half)
#pragma unroll
                for (int q = 0; q < 2; ++q) {
                    int n = wn0 + nj * 8 + tg2 + q;
                    int s = wm0 + mi * 16 + g + half * 8;
                    __half v = __float2half_rn(acc[mi][nj][half * 2 + q]);
                    sT[n * 136 + s] = *reinterpret_cast<unsigned short*>(&v);
                }
    __syncthreads();

#pragma unroll
    for (int i = 0; i < 4; ++i) {
        int v = tid + 256 * i;
        int col = v >> 4, seg = v & 15;
        uint4 d = *(uint4*)(sT + col * 136 + seg * 8);
        __half* dst = (col < 32)
            ? (__half*)gA + (((size_t)r * 32 + col) * S_DIM) + seg * 8
            : (__half*)gB + (((size_t)r * 32 + col - 32) * S_DIM) + seg * 8;
        *(uint4*)dst = d;
    }
}

// ------------------------- kernel 2: GEMM1 -------------------------
// P[(r,c),(t,e)] = sum_s A[rc][s] * B[te][s].  Block 64(M) x 128(N), warp 32x32,
// 8 warps (2m x 4n). K=128 as 2 x 64 cp.async stages. 3 CTAs/SM.
#define GS 72                             // 64 + 8 pad
#define ST_A (64 * GS)                    // 4608 ush per A plane
#define ST_TOT (ST_A + 128 * GS)          // 13824 ush per stage
#define G_SMEM (2 * ST_TOT * 2)           // 55296 B
#define PE_STRIDE 1032
__global__ __launch_bounds__(256, 3) void gemm1_kernel() {
    extern __shared__ unsigned short sm16[];
    unsigned short* sE = sm16;            // epilogue overlay: 8 x 1032 (in stage 0)

    const int tid = threadIdx.x;
    const int mb = blockIdx.y * 64, nb = blockIdx.x * 128;

    auto issue = [&](int st, int kc) {
        unsigned short* sA = sm16 + st * ST_TOT;
        unsigned short* sB = sA + ST_A;
#pragma unroll
        for (int i = 0; i < 2; ++i) {     // A: 64 rows x 8 segs
            int idx = tid + 256 * i;
            int row = idx >> 3, seg = idx & 7;
            cp16(sA + row * GS + seg * 8,
                 (const __half*)gA + (size_t)(mb + row) * S_DIM + kc + seg * 8);
        }
#pragma unroll
        for (int i = 0; i < 4; ++i) {     // B: 128 rows x 8 segs
            int idx = tid + 256 * i;
            int row = idx >> 3, seg = idx & 7;
            cp16(sB + row * GS + seg * 8,
                 (const __half*)gB + (size_t)(nb + row) * S_DIM + kc + seg * 8);
        }
        CP_COMMIT();
    };

    issue(0, 0);
    issue(1, 64);

    const int wid = tid >> 5, lane = tid & 31;
    const int wm0 = (wid & 1) * 32, wn0 = (wid >> 1) * 32;
    const int g = lane >> 2, tg2 = (lane & 3) * 2;

    float acc[2][4][4];
#pragma unroll
    for (int mi = 0; mi < 2; ++mi)
#pragma unroll
        for (int nj = 0; nj < 4; ++nj)
#pragma unroll
            for (int k = 0; k < 4; ++k) acc[mi][nj][k] = 0.f;

    CP_WAIT1();
    __syncthreads();

#pragma unroll
    for (int st = 0; st < 2; ++st) {
        unsigned short* sA = sm16 + st * ST_TOT;
        unsigned short* sB = sA + ST_A;
#pragma unroll
        for (int ks = 0; ks < 64; ks += 16) {
            unsigned a[2][4], b[4][2];
#pragma unroll
            for (int mi = 0; mi < 2; ++mi) {
                int base = (wm0 + mi * 16 + g) * GS + ks + tg2;
                a[mi][0] = lds2(sA + base);
                a[mi][1] = lds2(sA + base + 8 * GS);
                a[mi][2] = lds2(sA + base + 8);
                a[mi][3] = lds2(sA + base + 8 * GS + 8);
            }
#pragma unroll
            for (int nj = 0; nj < 4; ++nj) {
                int base = (wn0 + nj * 8 + g) * GS + ks + tg2;
                b[nj][0] = lds2(sB + base);
                b[nj][1] = lds2(sB + base + 8);
            }
#pragma unroll
            for (int mi = 0; mi < 2; ++mi)
#pragma unroll
                for (int nj = 0; nj < 4; ++nj)
                    mma16816h(acc[mi][nj], a[mi], b[nj]);
        }
        if (st == 0) {
            CP_WAIT0();
            __syncthreads();
        }
    }
    __syncthreads();   // all tile reads done before sE overlay

    // stage P tile: sE[rtl][c*32+e], rtl = r_local*4 + t_local (8 rows x 1024)
#pragma unroll
    for (int mi = 0; mi < 2; ++mi) {
#pragma unroll
        for (int nj = 0; nj < 4; ++nj) {
            int n = wn0 + nj * 8 + tg2;
            int t_local = n >> 5, e = n & 31;
#pragma unroll
            for (int half = 0; half < 2; ++half) {
                int m = wm0 + mi * 16 + g + half * 8;
                int r_local = m >> 5, c = m & 31;
                int rtl = r_local * 4 + t_local;
                __half h0 = __float2half_rn(acc[mi][nj][half * 2 + 0]);
                __half h1 = __float2half_rn(acc[mi][nj][half * 2 + 1]);
                unsigned hp = (unsigned)__half_as_ushort(h0) |
                              ((unsigned)__half_as_ushort(h1) << 16);
                *(unsigned*)(sE + rtl * PE_STRIDE + c * 32 + e) = hp;
            }
        }
    }
    __syncthreads();

    // coalesced write: 8 complete P rows of 2KB
    const int r_base = blockIdx.y * 2, t_base = blockIdx.x * 4;
#pragma unroll
    for (int i = 0; i < 4; ++i) {
        int v = tid + 256 * i;
        int row = v >> 7, seg = v & 127;
        uint4 d = *(uint4*)(sE + row * PE_STRIDE + seg * 8);
        size_t rt = (((size_t)(r_base + (row >> 2))) << 8) + t_base + (row & 3);
        *(uint4*)((__half*)gP + rt * CE_DIM + seg * 8) = d;
    }
}

// ------------------------- kernel 3: GEMM2 -------------------------
// out[(r,t),z] = sum_ce P[rt][ce] * Wt[z][ce]. M=65536, N=128, K=1024.
// Block 64(M) x 128(N), warp 32x32, 8 warps, K-chunk 64 double-buffered. 3 CTAs/SM.
__global__ __launch_bounds__(256, 3) void gemm2_kernel(float* __restrict__ out) {
    extern __shared__ unsigned short sm16[];

    const int tid = threadIdx.x;
    const size_t mb = (size_t)blockIdx.x * 64;
    const int wid = tid >> 5, lane = tid & 31;
    const int wm0 = (wid & 1) * 32, wn0 = (wid >> 1) * 32;
    const int g = lane >> 2, tg2 = (lane & 3) * 2;

    auto issue = [&](int st, int kc) {
        unsigned short* sA = sm16 + st * ST_TOT;
        unsigned short* sB = sA + ST_A;
#pragma unroll
        for (int i = 0; i < 2; ++i) {     // A: 64 rows (P)
            int idx = tid + 256 * i;
            int row = idx >> 3, seg = idx & 7;
            cp16(sA + row * GS + seg * 8,
                 (const __half*)gP + (mb + row) * CE_DIM + kc + seg * 8);
        }
#pragma unroll
        for (int i = 0; i < 4; ++i) {     // B: 128 z rows (Wt)
            int idx = tid + 256 * i;
            int row = idx >> 3, seg = idx & 7;
            cp16(sB + row * GS + seg * 8,
                 (const __half*)gWt + (size_t)row * CE_DIM + kc + seg * 8);
        }
        CP_COMMIT();
    };

    float acc[2][4][4];
#pragma unroll
    for (int mi = 0; mi < 2; ++mi)
#pragma unroll
        for (int nj = 0; nj < 4; ++nj)
#pragma unroll
            for (int k = 0; k < 4; ++k) acc[mi][nj][k] = 0.f;

    issue(0, 0);

    for (int kci = 0; kci < 16; ++kci) {
        const int cur = kci & 1;
        if (kci + 1 < 16) {
            issue(cur ^ 1, (kci + 1) * 64);
            CP_WAIT1();
        } else {
            CP_WAIT0();
        }
        __syncthreads();

        unsigned short* sA = sm16 + cur * ST_TOT;
        unsigned short* sB = sA + ST_A;
#pragma unroll
        for (int ks = 0; ks < 64; ks += 16) {
            unsigned a[2][4], b[4][2];
#pragma unroll
            for (int mi = 0; mi < 2; ++mi) {
                int base = (wm0 + mi * 16 + g) * GS + ks + tg2;
                a[mi][0] = lds2(sA + base);
                a[mi][1] = lds2(sA + base + 8 * GS);
                a[mi][2] = lds2(sA + base + 8);
                a[mi][3] = lds2(sA + base + 8 * GS + 8);
            }
#pragma unroll
            for (int nj = 0; nj < 4; ++nj) {
                int base = (wn0 + nj * 8 + g) * GS + ks + tg2;
                b[nj][0] = lds2(sB + base);
                b[nj][1] = lds2(sB + base + 8);
            }
#pragma unroll
            for (int mi = 0; mi < 2; ++mi)
#pragma unroll
                for (int nj = 0; nj < 4; ++nj)
                    mma16816h(acc[mi][nj], a[mi], b[nj]);
        }
        __syncthreads();
    }

#pragma unroll
    for (int mi = 0; mi < 2; ++mi) {
#pragma unroll
        for (int nj = 0; nj < 4; ++nj) {
            int n = wn0 + nj * 8 + tg2;
#pragma unroll
            for (int half = 0; half < 2; ++half) {
                size_t m = mb + wm0 + mi * 16 + g + half * 8;
                float2 v;
                v.x = acc[mi][nj][half * 2 + 0];
                v.y = acc[mi][nj][half * 2 + 1];
                *(float2*)(out + m * CZ_DIM + n) = v;
            }
        }
    }
}

// ------------------------- launch -------------------------
extern "C" void kernel_launch(void* const* d_in, const int* in_sizes, int n_in,
                              void* d_out, int out_size) {
    const float* msa = (const float*)d_in[0];
    const float* lw  = (const float*)d_in[1];
    const float* rw  = (const float*)d_in[2];
    const float* ow  = (const float*)d_in[3];
    float* out = (float*)d_out;

    (void)in_sizes; (void)n_in; (void)out_size;

    cudaFuncSetAttribute((const void*)proj_tc_kernel,
                         cudaFuncAttributeMaxDynamicSharedMemorySize, PROJ_SMEM);
    cudaFuncSetAttribute((const void*)gemm1_kernel,
                         cudaFuncAttributeMaxDynamicSharedMemorySize, G_SMEM);
    cudaFuncSetAttribute((const void*)gemm2_kernel,
                         cudaFuncAttributeMaxDynamicSharedMemorySize, G_SMEM);

    prep_kernel<<<(CE_DIM * CZ_DIM + 255) / 256, 256>>>(lw, rw, ow);
    proj_tc_kernel<<<R_DIM, 256, PROJ_SMEM>>>(msa);
    gemm1_kernel<<<dim3(64, 128), 256, G_SMEM>>>();
    gemm2_kernel<<<RT_DIM / 64, 256, G_SMEM>>>(out);
}

// round 13
// speedup vs baseline: 1.8968x; 1.0471x over previous
#include <cuda_runtime.h>
#include <cuda_fp16.h>
#include <cuda_bf16.h>
#include <cstdint>

// Problem dims: msa [1,128,256,256] f32; left_w/right_w [256,32]; out_w [1024,128]
// out [1,256,256,128] f32.
#define S_DIM 128
#define R_DIM 256
#define M_DIM 256
#define C_DIM 32
#define CZ_DIM 128
#define RC_DIM 8192          // R*C
#define CE_DIM 1024          // C*C
#define RT_DIM 65536         // R*R

// ------------------------- device scratch (no allocs allowed) -------------------------
__device__ __half gA[RC_DIM * S_DIM];                 // left  [rc][s] fp16
__device__ __half gB[RC_DIM * S_DIM];                 // right [te][s] fp16
__device__ __half gP[(size_t)RT_DIM * CE_DIM];        // P [rt][ce] fp16
__device__ __half gWt[CZ_DIM * CE_DIM];               // W^T [z][ce] fp16 (gemm2)
__device__ unsigned short gWph[64 * M_DIM];           // proj weights hi [n][m] bf16
__device__ unsigned short gWpl[64 * M_DIM];           // proj weights lo [n][m] bf16

// ------------------------- helpers -------------------------
__device__ __forceinline__ unsigned lds2(const unsigned short* p) {
    return *reinterpret_cast<const unsigned*>(p);
}

__device__ __forceinline__ void mma16816h(float* c, const unsigned* a, const unsigned* b) {
    asm volatile(
        "mma.sync.aligned.m16n8k16.row.col.f32.f16.f16.f32 "
        "{%0,%1,%2,%3}, {%4,%5,%6,%7}, {%8,%9}, {%0,%1,%2,%3};\n"
        : "+f"(c[0]), "+f"(c[1]), "+f"(c[2]), "+f"(c[3])
        : "r"(a[0]), "r"(a[1]), "r"(a[2]), "r"(a[3]), "r"(b[0]), "r"(b[1]));
}

__device__ __forceinline__ void mma16816bf(float* c, const unsigned* a, const unsigned* b) {
    asm volatile(
        "mma.sync.aligned.m16n8k16.row.col.f32.bf16.bf16.f32 "
        "{%0,%1,%2,%3}, {%4,%5,%6,%7}, {%8,%9}, {%0,%1,%2,%3};\n"
        : "+f"(c[0]), "+f"(c[1]), "+f"(c[2]), "+f"(c[3])
        : "r"(a[0]), "r"(a[1]), "r"(a[2]), "r"(a[3]), "r"(b[0]), "r"(b[1]));
}

// .cg: bypass L1 allocation — tile data is consumed from smem, never re-read via L1.
__device__ __forceinline__ void cp16(void* smem, const void* g) {
    unsigned s = (unsigned)__cvta_generic_to_shared(smem);
    asm volatile("cp.async.cg.shared.global [%0], [%1], 16;\n" :: "r"(s), "l"(g));
}
#define CP_COMMIT() asm volatile("cp.async.commit_group;\n" ::: "memory")
#define CP_WAIT0()  asm volatile("cp.async.wait_group 0;\n" ::: "memory")
#define CP_WAIT1()  asm volatile("cp.async.wait_group 1;\n" ::: "memory")

__device__ __forceinline__ void bf_split(float x, unsigned short& h, unsigned short& l) {
    __nv_bfloat16 hb = __float2bfloat16_rn(x);
    h = *reinterpret_cast<unsigned short*>(&hb);
    __nv_bfloat16 lb = __float2bfloat16_rn(x - __bfloat162float(hb));
    l = *reinterpret_cast<unsigned short*>(&lb);
}

// ------------------------- kernel 0: weight prep -------------------------
__global__ __launch_bounds__(256) void prep_kernel(const float* __restrict__ lw,
                                                   const float* __restrict__ rw,
                                                   const float* __restrict__ ow) {
    int idx = blockIdx.x * 256 + threadIdx.x;
    if (idx < 64 * M_DIM) {
        int n = idx >> 8, m = idx & 255;
        float x = (n < 32) ? lw[m * 32 + n] : rw[m * 32 + (n - 32)];
        unsigned short h, l;
        bf_split(x, h, l);
        gWph[n * M_DIM + m] = h;
        gWpl[n * M_DIM + m] = l;
    }
    if (idx < CE_DIM * CZ_DIM) {     // idx = ce*128 + z
        int z = idx & 127, ce = idx >> 7;
        gWt[(size_t)z * CE_DIM + ce] = __float2half_rn(ow[idx]);
    }
}

// ------------------------- kernel 1: projection (tensor cores) -------------------------
#define PWS 264          // 256 + 8 pad
#define P_SWH 0
#define P_SWL (64 * PWS)
#define P_SAH (2 * 64 * PWS)
#define P_SAL (P_SAH + 128 * PWS)
#define PROJ_SMEM ((P_SAL + 128 * PWS) * 2)   // 202752 B
__global__ __launch_bounds__(256) void proj_tc_kernel(const float* __restrict__ msa) {
    extern __shared__ unsigned short sm16[];
    unsigned short* sWh = sm16 + P_SWH;
    unsigned short* sWl = sm16 + P_SWL;
    unsigned short* sAh = sm16 + P_SAH;
    unsigned short* sAl = sm16 + P_SAL;
    unsigned short* sT  = sm16 + P_SAH;

    const int tid = threadIdx.x;
    const int r = blockIdx.x;

#pragma unroll
    for (int i = 0; i < 16; ++i) {
        int idx = tid + 256 * i;
        int plane = idx >> 11, rem = idx & 2047;
        int n = rem >> 5, seg = rem & 31;
        unsigned short* dst = (plane ? sWl : sWh) + n * PWS + seg * 8;
        const unsigned short* src = (plane ? gWpl : gWph) + n * M_DIM + seg * 8;
        cp16(dst, src);
    }
    CP_COMMIT();

#pragma unroll
    for (int i = 0; i < 32; ++i) {
        int v = tid + 256 * i;
        int row = v >> 6, col4 = v & 63;
        const float4 x = *(const float4*)(msa + (((size_t)(row * R_DIM + r)) << 8) + col4 * 4);
        unsigned short h0, h1, h2, h3, l0, l1, l2, l3;
        bf_split(x.x, h0, l0); bf_split(x.y, h1, l1);
        bf_split(x.z, h2, l2); bf_split(x.w, h3, l3);
        int ofs = row * PWS + col4 * 4;
        *(unsigned*)(sAh + ofs)     = (unsigned)h0 | ((unsigned)h1 << 16);
        *(unsigned*)(sAh + ofs + 2) = (unsigned)h2 | ((unsigned)h3 << 16);
        *(unsigned*)(sAl + ofs)     = (unsigned)l0 | ((unsigned)l1 << 16);
        *(unsigned*)(sAl + ofs + 2) = (unsigned)l2 | ((unsigned)l3 << 16);
    }
    CP_WAIT0();
    __syncthreads();

    const int wid = tid >> 5, lane = tid & 31;
    const int g = lane >> 2, tg2 = (lane & 3) * 2;
    const int wm0 = (wid & 3) * 32, wn0 = (wid >> 2) * 32;

    float acc[2][4][4];
#pragma unroll
    for (int mi = 0; mi < 2; ++mi)
#pragma unroll
        for (int nj = 0; nj < 4; ++nj)
#pragma unroll
            for (int k = 0; k < 4; ++k) acc[mi][nj][k] = 0.f;

#pragma unroll
    for (int ks = 0; ks < 256; ks += 16) {
        unsigned ah[2][4], al[2][4], bh[4][2], bl[4][2];
#pragma unroll
        for (int mi = 0; mi < 2; ++mi) {
            int base = (wm0 + mi * 16 + g) * PWS + ks + tg2;
            ah[mi][0] = lds2(sAh + base);
            ah[mi][1] = lds2(sAh + base + 8 * PWS);
            ah[mi][2] = lds2(sAh + base + 8);
            ah[mi][3] = lds2(sAh + base + 8 * PWS + 8);
            al[mi][0] = lds2(sAl + base);
            al[mi][1] = lds2(sAl + base + 8 * PWS);
            al[mi][2] = lds2(sAl + base + 8);
            al[mi][3] = lds2(sAl + base + 8 * PWS + 8);
        }
#pragma unroll
        for (int nj = 0; nj < 4; ++nj) {
            int base = (wn0 + nj * 8 + g) * PWS + ks + tg2;
            bh[nj][0] = lds2(sWh + base);
            bh[nj][1] = lds2(sWh + base + 8);
            bl[nj][0] = lds2(sWl + base);
            bl[nj][1] = lds2(sWl + base + 8);
        }
#pragma unroll
        for (int mi = 0; mi < 2; ++mi)
#pragma unroll
            for (int nj = 0; nj < 4; ++nj) {
                mma16816bf(acc[mi][nj], ah[mi], bh[nj]);
                mma16816bf(acc[mi][nj], ah[mi], bl[nj]);
                mma16816bf(acc[mi][nj], al[mi], bh[nj]);
            }
    }
    __syncthreads();

#pragma unroll
    for (int mi = 0; mi < 2; ++mi)
#pragma unroll
        for (int nj = 0; nj < 4; ++nj)
#pragma unroll
            for (int half = 0; half < 2; ++half)
#pragma unroll
                for (int q = 0; q < 2; ++q) {
                    int n = wn0 + nj * 8 + tg2 + q;
                    int s = wm0 + mi * 16 + g + half * 8;
                    __half v = __float2half_rn(acc[mi][nj][half * 2 + q]);
                    sT[n * 136 + s] = *reinterpret_cast<unsigned short*>(&v);
                }
    __syncthreads();

#pragma unroll
    for (int i = 0; i < 4; ++i) {
        int v = tid + 256 * i;
        int col = v >> 4, seg = v & 15;
        uint4 d = *(uint4*)(sT + col * 136 + seg * 8);
        __half* dst = (col < 32)
            ? (__half*)gA + (((size_t)r * 32 + col) * S_DIM) + seg * 8
            : (__half*)gB + (((size_t)r * 32 + col - 32) * S_DIM) + seg * 8;
        *(uint4*)dst = d;
    }
}

// ------------------------- kernel 2: GEMM1 -------------------------
// P[(r,c),(t,e)] = sum_s A[rc][s] * B[te][s].  Block 64(M) x 128(N), warp 32x32,
// 8 warps (2m x 4n). K=128 as 2 x 64 cp.async stages. 3 CTAs/SM.
#define GS 72                             // 64 + 8 pad
#define ST_A (64 * GS)
#define ST_TOT (ST_A + 128 * GS)
#define G_SMEM (2 * ST_TOT * 2)           // 55296 B
#define PE_STRIDE 1032
__global__ __launch_bounds__(256, 3) void gemm1_kernel() {
    extern __shared__ unsigned short sm16[];
    unsigned short* sE = sm16;            // epilogue overlay: lives in stage-0 region

    const int tid = threadIdx.x;
    const int mb = blockIdx.y * 64, nb = blockIdx.x * 128;

    auto issue = [&](int st, int kc) {
        unsigned short* sA = sm16 + st * ST_TOT;
        unsigned short* sB = sA + ST_A;
#pragma unroll
        for (int i = 0; i < 2; ++i) {
            int idx = tid + 256 * i;
            int row = idx >> 3, seg = idx & 7;
            cp16(sA + row * GS + seg * 8,
                 (const __half*)gA + (size_t)(mb + row) * S_DIM + kc + seg * 8);
        }
#pragma unroll
        for (int i = 0; i < 4; ++i) {
            int idx = tid + 256 * i;
            int row = idx >> 3, seg = idx & 7;
            cp16(sB + row * GS + seg * 8,
                 (const __half*)gB + (size_t)(nb + row) * S_DIM + kc + seg * 8);
        }
        CP_COMMIT();
    };

    issue(0, 0);
    issue(1, 64);

    const int wid = tid >> 5, lane = tid & 31;
    const int wm0 = (wid & 1) * 32, wn0 = (wid >> 1) * 32;
    const int g = lane >> 2, tg2 = (lane & 3) * 2;

    float acc[2][4][4];
#pragma unroll
    for (int mi = 0; mi < 2; ++mi)
#pragma unroll
        for (int nj = 0; nj < 4; ++nj)
#pragma unroll
            for (int k = 0; k < 4; ++k) acc[mi][nj][k] = 0.f;

    CP_WAIT1();
    __syncthreads();

#pragma unroll
    for (int st = 0; st < 2; ++st) {
        unsigned short* sA = sm16 + st * ST_TOT;
        unsigned short* sB = sA + ST_A;
#pragma unroll
        for (int ks = 0; ks < 64; ks += 16) {
            unsigned a[2][4], b[4][2];
#pragma unroll
            for (int mi = 0; mi < 2; ++mi) {
                int base = (wm0 + mi * 16 + g) * GS + ks + tg2;
                a[mi][0] = lds2(sA + base);
                a[mi][1] = lds2(sA + base + 8 * GS);
                a[mi][2] = lds2(sA + base + 8);
                a[mi][3] = lds2(sA + base + 8 * GS + 8);
            }
#pragma unroll
            for (int nj = 0; nj < 4; ++nj) {
                int base = (wn0 + nj * 8 + g) * GS + ks + tg2;
                b[nj][0] = lds2(sB + base);
                b[nj][1] = lds2(sB + base + 8);
            }
#pragma unroll
            for (int mi = 0; mi < 2; ++mi)
#pragma unroll
                for (int nj = 0; nj < 4; ++nj)
                    mma16816h(acc[mi][nj], a[mi], b[nj]);
        }
        if (st == 0) {
            CP_WAIT0();
            __syncthreads();   // all warps done with stage 0; stage-0 overlay now safe
        }
    }
    // NOTE: no barrier needed here — sE overlays stage-0 only (8*1032 < ST_TOT),
    // all stage-0 reads completed before the mid-loop barrier; stage-1 reads are disjoint.

    // stage P tile: sE[rtl][c*32+e], rtl = r_local*4 + t_local (8 rows x 1024)
#pragma unroll
    for (int mi = 0; mi < 2; ++mi) {
#pragma unroll
        for (int nj = 0; nj < 4; ++nj) {
            int n = wn0 + nj * 8 + tg2;
            int t_local = n >> 5, e = n & 31;
#pragma unroll
            for (int half = 0; half < 2; ++half) {
                int m = wm0 + mi * 16 + g + half * 8;
                int r_local = m >> 5, c = m & 31;
                int rtl = r_local * 4 + t_local;
                __half h0 = __float2half_rn(acc[mi][nj][half * 2 + 0]);
                __half h1 = __float2half_rn(acc[mi][nj][half * 2 + 1]);
                unsigned hp = (unsigned)__half_as_ushort(h0) |
                              ((unsigned)__half_as_ushort(h1) << 16);
                *(unsigned*)(sE + rtl * PE_STRIDE + c * 32 + e) = hp;
            }
        }
    }
    __syncthreads();

    // coalesced write: 8 complete P rows of 2KB
    const int r_base = blockIdx.y * 2, t_base = blockIdx.x * 4;
#pragma unroll
    for (int i = 0; i < 4; ++i) {
        int v = tid + 256 * i;
        int row = v >> 7, seg = v & 127;
        uint4 d = *(uint4*)(sE + row * PE_STRIDE + seg * 8);
        size_t rt = (((size_t)(r_base + (row >> 2))) << 8) + t_base + (row & 3);
        *(uint4*)((__half*)gP + rt * CE_DIM + seg * 8) = d;
    }
}

// ------------------------- kernel 3: GEMM2 -------------------------
// out[(r,t),z] = sum_ce P[rt][ce] * Wt[z][ce]. M=65536, N=128, K=1024.
// Block 64(M) x 128(N), warp 32x32, 8 warps, K-chunk 64 double-buffered with
// SINGLE sync per chunk: wait(0) -> sync -> issue next -> compute. 3 CTAs/SM.
__global__ __launch_bounds__(256, 3) void gemm2_kernel(float* __restrict__ out) {
    extern __shared__ unsigned short sm16[];

    const int tid = threadIdx.x;
    const size_t mb = (size_t)blockIdx.x * 64;
    const int wid = tid >> 5, lane = tid & 31;
    const int wm0 = (wid & 1) * 32, wn0 = (wid >> 1) * 32;
    const int g = lane >> 2, tg2 = (lane & 3) * 2;

    auto issue = [&](int st, int kc) {
        unsigned short* sA = sm16 + st * ST_TOT;
        unsigned short* sB = sA + ST_A;
#pragma unroll
        for (int i = 0; i < 2; ++i) {     // A: 64 rows (P)
            int idx = tid + 256 * i;
            int row = idx >> 3, seg = idx & 7;
            cp16(sA + row * GS + seg * 8,
                 (const __half*)gP + (mb + row) * CE_DIM + kc + seg * 8);
        }
#pragma unroll
        for (int i = 0; i < 4; ++i) {     // B: 128 z rows (Wt)
            int idx = tid + 256 * i;
            int row = idx >> 3, seg = idx & 7;
            cp16(sB + row * GS + seg * 8,
                 (const __half*)gWt + (size_t)row * CE_DIM + kc + seg * 8);
        }
        CP_COMMIT();
    };

    float acc[2][4][4];
#pragma unroll
    for (int mi = 0; mi < 2; ++mi)
#pragma unroll
        for (int nj = 0; nj < 4; ++nj)
#pragma unroll
            for (int k = 0; k < 4; ++k) acc[mi][nj][k] = 0.f;

    issue(0, 0);

    for (int kci = 0; kci < 16; ++kci) {
        const int cur = kci & 1;
        CP_WAIT0();          // chunk kci resident
        __syncthreads();     // + every warp finished chunk kci-1 -> other buffer reusable
        if (kci + 1 < 16)
            issue(cur ^ 1, (kci + 1) * 64);   // overlaps with compute below

        unsigned short* sA = sm16 + cur * ST_TOT;
        unsigned short* sB = sA + ST_A;
#pragma unroll
        for (int ks = 0; ks < 64; ks += 16) {
            unsigned a[2][4], b[4][2];
#pragma unroll
            for (int mi = 0; mi < 2; ++mi) {
                int base = (wm0 + mi * 16 + g) * GS + ks + tg2;
                a[mi][0] = lds2(sA + base);
                a[mi][1] = lds2(sA + base + 8 * GS);
                a[mi][2] = lds2(sA + base + 8);
                a[mi][3] = lds2(sA + base + 8 * GS + 8);
            }
#pragma unroll
            for (int nj = 0; nj < 4; ++nj) {
                int base = (wn0 + nj * 8 + g) * GS + ks + tg2;
                b[nj][0] = lds2(sB + base);
                b[nj][1] = lds2(sB + base + 8);
            }
#pragma unroll
            for (int mi = 0; mi < 2; ++mi)
#pragma unroll
                for (int nj = 0; nj < 4; ++nj)
                    mma16816h(acc[mi][nj], a[mi], b[nj]);
        }
    }

#pragma unroll
    for (int mi = 0; mi < 2; ++mi) {
#pragma unroll
        for (int nj = 0; nj < 4; ++nj) {
            int n = wn0 + nj * 8 + tg2;
#pragma unroll
            for (int half = 0; half < 2; ++half) {
                size_t m = mb + wm0 + mi * 16 + g + half * 8;
                float2 v;
                v.x = acc[mi][nj][half * 2 + 0];
                v.y = acc[mi][nj][half * 2 + 1];
                *(float2*)(out + m * CZ_DIM + n) = v;
            }
        }
    }
}

// ------------------------- launch -------------------------
extern "C" void kernel_launch(void* const* d_in, const int* in_sizes, int n_in,
                              void* d_out, int out_size) {
    const float* msa = (const float*)d_in[0];
    const float* lw  = (const float*)d_in[1];
    const float* rw  = (const float*)d_in[2];
    const float* ow  = (const float*)d_in[3];
    float* out = (float*)d_out;

    (void)in_sizes; (void)n_in; (void)out_size;

    cudaFuncSetAttribute((const void*)proj_tc_kernel,
                         cudaFuncAttributeMaxDynamicSharedMemorySize, PROJ_SMEM);
    cudaFuncSetAttribute((const void*)gemm1_kernel,
                         cudaFuncAttributeMaxDynamicSharedMemorySize, G_SMEM);
    cudaFuncSetAttribute((const void*)gemm2_kernel,
                         cudaFuncAttributeMaxDynamicSharedMemorySize, G_SMEM);

    prep_kernel<<<(CE_DIM * CZ_DIM + 255) / 256, 256>>>(lw, rw, ow);
    proj_tc_kernel<<<R_DIM, 256, PROJ_SMEM>>>(msa);
    gemm1_kernel<<<dim3(64, 128), 256, G_SMEM>>>();
    gemm2_kernel<<<RT_DIM / 64, 256, G_SMEM>>>(out);
}